// round 2
// baseline (speedup 1.0000x reference)
#include <cuda_runtime.h>

typedef unsigned long long ull;

#define LOG2E_F  1.4426950408889634f
#define LOG2PI_F 1.8378770664093453f
#define KCOMP 8
#define TPB 256
#define ELEMS_PER_THREAD 8
#define ELEMS_PER_BLOCK (TPB * ELEMS_PER_THREAD)  // 2048

// ---- packed f32x2 helpers (sm_100+ 64-bit fp32 pipe) ----
__device__ __forceinline__ ull pk2(float a, float b) {
    ull r; asm("mov.b64 %0, {%1, %2};" : "=l"(r) : "f"(a), "f"(b)); return r;
}
__device__ __forceinline__ void upk2(ull v, float& a, float& b) {
    asm("mov.b64 {%0, %1}, %2;" : "=f"(a), "=f"(b) : "l"(v));
}
__device__ __forceinline__ ull add2(ull a, ull b) {
    ull r; asm("add.rn.f32x2 %0, %1, %2;" : "=l"(r) : "l"(a), "l"(b)); return r;
}
__device__ __forceinline__ ull fma2(ull a, ull b, ull c) {
    ull r; asm("fma.rn.f32x2 %0, %1, %2, %3;" : "=l"(r) : "l"(a), "l"(b), "l"(c)); return r;
}
__device__ __forceinline__ float ex2f_fast(float x) {
    float r; asm("ex2.approx.ftz.f32 %0, %1;" : "=f"(r) : "f"(x)); return r;
}
__device__ __forceinline__ float rcpf_fast(float x) {
    float r; asm("rcp.approx.ftz.f32 %0, %1;" : "=f"(r) : "f"(x)); return r;
}

__global__ __launch_bounds__(TPB) void gmm_hscore_kernel(
    const float4* __restrict__ x4,
    const float*  __restrict__ mean,
    const float*  __restrict__ logvar,
    const float*  __restrict__ logweight,
    float4*       __restrict__ out4)
{
    // Per-k packed constants in shared:
    //   exponent: T = a*x^2 + b*x + c   (base-2, weight folded in)
    //     a = -0.5*iv*log2e
    //     b = -2*a*mu = iv*mu*log2e
    //     c = a*mu^2 + (lw - 0.5*(lv+LOG2PI))*log2e
    //   score:    S = -iv*x + iv*mu = fma(niv, x, ivmu)
    __shared__ ull sA[KCOMP], sB[KCOMP], sC[KCOMP], sNIV[KCOMP], sIVMU[KCOMP];

    const int t = threadIdx.x;
    if (t < KCOMP) {
        float lv = logvar[t];
        float mu = mean[t];
        float lw = logweight[t];
        float iv = ex2f_fast(-lv * LOG2E_F);           // exp(-lv) = 1/var
        float a  = -0.5f * iv * LOG2E_F;
        float b  = -2.0f * a * mu;
        float c  = fmaf(a, mu * mu, (lw - 0.5f * (lv + LOG2PI_F)) * LOG2E_F);
        sA[t]    = pk2(a, a);
        sB[t]    = pk2(b, b);
        sC[t]    = pk2(c, c);
        sNIV[t]  = pk2(-iv, -iv);
        sIVMU[t] = pk2(iv * mu, iv * mu);
    }
    __syncthreads();

    // ---- load 8 elements (two coalesced float4) ----
    const int base = blockIdx.x * (2 * TPB) + t;   // in float4 units
    float4 xa = x4[base];
    float4 xb = x4[base + TPB];

    ull X[4];
    X[0] = pk2(xa.x, xa.y);
    X[1] = pk2(xa.z, xa.w);
    X[2] = pk2(xb.x, xb.y);
    X[3] = pk2(xb.z, xb.w);

    ull MP[4], MD[4], DD[4];
    const ull Z = pk2(0.0f, 0.0f);
    #pragma unroll
    for (int p = 0; p < 4; p++) { MP[p] = Z; MD[p] = Z; DD[p] = Z; }

    // ---- main loop: k outer (constants from shared), 4 packed pairs inner ----
    #pragma unroll
    for (int k = 0; k < KCOMP; k++) {
        const ull a2  = sA[k];
        const ull b2  = sB[k];
        const ull c2  = sC[k];
        const ull nv2 = sNIV[k];
        const ull im2 = sIVMU[k];
        #pragma unroll
        for (int p = 0; p < 4; p++) {
            ull H = fma2(a2, X[p], b2);        // a*x + b
            ull T = fma2(H, X[p], c2);         // a*x^2 + b*x + c
            float t0, t1; upk2(T, t0, t1);
            float e0 = ex2f_fast(t0);
            float e1 = ex2f_fast(t1);
            ull P = pk2(e0, e1);               // weight*pdf contribution
            MP[p] = add2(MP[p], P);            // mpdf
            ull S = fma2(nv2, X[p], im2);      // s = -(x-mu)/var
            MD[p] = fma2(P, S, MD[p]);         // mdpdf
            ull U = fma2(S, S, nv2);           // s^2 - 1/var
            DD[p] = fma2(P, U, DD[p]);         // ddpdf
        }
    }

    // ---- epilogue: hscore = -0.5*(md/mp)^2 + dd/mp ----
    float h[8];
    #pragma unroll
    for (int p = 0; p < 4; p++) {
        float mp0, mp1, md0, md1, dd0, dd1;
        upk2(MP[p], mp0, mp1);
        upk2(MD[p], md0, md1);
        upk2(DD[p], dd0, dd1);
        float r0 = rcpf_fast(mp0);
        float r1 = rcpf_fast(mp1);
        float dl0 = md0 * r0;
        float dl1 = md1 * r1;
        h[2*p+0] = fmaf(-0.5f * dl0, dl0, dd0 * r0);
        h[2*p+1] = fmaf(-0.5f * dl1, dl1, dd1 * r1);
    }

    float4 oa = make_float4(h[0], h[1], h[2], h[3]);
    float4 ob = make_float4(h[4], h[5], h[6], h[7]);
    out4[base]       = oa;
    out4[base + TPB] = ob;
}

extern "C" void kernel_launch(void* const* d_in, const int* in_sizes, int n_in,
                              void* d_out, int out_size) {
    const float4* x4        = (const float4*)d_in[0];
    const float*  mean      = (const float*)d_in[1];
    const float*  logvar    = (const float*)d_in[2];
    const float*  logweight = (const float*)d_in[3];
    float4*       out4      = (float4*)d_out;

    int n = in_sizes[0];                      // 4194304, divisible by 2048
    int blocks = n / ELEMS_PER_BLOCK;
    gmm_hscore_kernel<<<blocks, TPB>>>(x4, mean, logvar, logweight, out4);
}

// round 3
// speedup vs baseline: 1.0972x; 1.0972x over previous
#include <cuda_runtime.h>

typedef unsigned long long ull;

#define LOG2E_F  1.4426950408889634f
#define LOG2PI_F 1.8378770664093453f
#define LN2_F    0.6931471805599453f
#define LN2SQ_F  0.4804530139182014f
#define KCOMP 8
#define TPB 256
#define ELEMS_PER_THREAD 4          // one float4 per thread
#define ELEMS_PER_BLOCK (TPB * ELEMS_PER_THREAD)  // 1024

// ---- packed f32x2 helpers (sm_100+ 64-bit fp32 pipe) ----
__device__ __forceinline__ ull pk2(float a, float b) {
    ull r; asm("mov.b64 %0, {%1, %2};" : "=l"(r) : "f"(a), "f"(b)); return r;
}
__device__ __forceinline__ void upk2(ull v, float& a, float& b) {
    asm("mov.b64 {%0, %1}, %2;" : "=f"(a), "=f"(b) : "l"(v));
}
__device__ __forceinline__ ull add2(ull a, ull b) {
    ull r; asm("add.rn.f32x2 %0, %1, %2;" : "=l"(r) : "l"(a), "l"(b)); return r;
}
__device__ __forceinline__ ull fma2(ull a, ull b, ull c) {
    ull r; asm("fma.rn.f32x2 %0, %1, %2, %3;" : "=l"(r) : "l"(a), "l"(b), "l"(c)); return r;
}
// EX2 on both halves of a packed pair, single asm block (lets ptxas keep
// everything in one register pair without extra MOVs).
__device__ __forceinline__ ull ex2_pair(ull t) {
    ull r;
    asm("{\n\t"
        ".reg .f32 lo, hi;\n\t"
        "mov.b64 {lo, hi}, %1;\n\t"
        "ex2.approx.ftz.f32 lo, lo;\n\t"
        "ex2.approx.ftz.f32 hi, hi;\n\t"
        "mov.b64 %0, {lo, hi};\n\t"
        "}" : "=l"(r) : "l"(t));
    return r;
}
__device__ __forceinline__ float ex2f_fast(float x) {
    float r; asm("ex2.approx.ftz.f32 %0, %1;" : "=f"(r) : "f"(x)); return r;
}
__device__ __forceinline__ float rcpf_fast(float x) {
    float r; asm("rcp.approx.ftz.f32 %0, %1;" : "=f"(r) : "f"(x)); return r;
}

__global__ __launch_bounds__(TPB, 6) void gmm_hscore_kernel(
    const float4* __restrict__ x4,
    const float*  __restrict__ mean,
    const float*  __restrict__ logvar,
    const float*  __restrict__ logweight,
    float4*       __restrict__ out4)
{
    // Per-k packed constants (4 per k):
    //   exponent (base 2, weight folded):  T = a*x^2 + b*x + c
    //     a = -0.5*iv*log2e ; b = -2*a*mu ; c = a*mu^2 + (lw - 0.5*(lv+LOG2PI))*log2e
    //   score (scaled):  S' = a*x + H  where H = a*x + b   (S = ln2 * S')
    //   nvs = -iv / ln2^2   so that  ln2^2*(S'^2 + nvs) = S^2 - iv
    __shared__ ull sA[KCOMP], sB[KCOMP], sC[KCOMP], sNVS[KCOMP];

    const int t = threadIdx.x;
    if (t < KCOMP) {
        float lv = logvar[t];
        float mu = mean[t];
        float lw = logweight[t];
        float iv = ex2f_fast(-lv * LOG2E_F);           // exp(-lv) = 1/var
        float a  = -0.5f * iv * LOG2E_F;
        float b  = -2.0f * a * mu;
        float c  = fmaf(a, mu * mu, (lw - 0.5f * (lv + LOG2PI_F)) * LOG2E_F);
        float nvs = -iv * (1.0f / LN2SQ_F);
        sA[t]   = pk2(a, a);
        sB[t]   = pk2(b, b);
        sC[t]   = pk2(c, c);
        sNVS[t] = pk2(nvs, nvs);
    }
    __syncthreads();

    // ---- load 4 elements (one coalesced float4) ----
    const int base = blockIdx.x * TPB + t;   // in float4 units
    float4 xa = x4[base];

    ull X0 = pk2(xa.x, xa.y);
    ull X1 = pk2(xa.z, xa.w);

    const ull Z = pk2(0.0f, 0.0f);
    ull MP0 = Z, MP1 = Z, MD0 = Z, MD1 = Z, DD0 = Z, DD1 = Z;

    // ---- main loop: k outer (constants from shared), 2 packed pairs inner ----
    #pragma unroll
    for (int k = 0; k < KCOMP; k++) {
        const ull a2 = sA[k];
        const ull b2 = sB[k];
        const ull c2 = sC[k];
        const ull v2 = sNVS[k];

        ull H0 = fma2(a2, X0, b2);
        ull H1 = fma2(a2, X1, b2);
        ull T0 = fma2(H0, X0, c2);
        ull T1 = fma2(H1, X1, c2);
        ull P0 = ex2_pair(T0);                // weight*pdf
        ull P1 = ex2_pair(T1);
        ull S0 = fma2(a2, X0, H0);            // S' = 2a*x + b  (= S/ln2)
        ull S1 = fma2(a2, X1, H1);
        MP0 = add2(MP0, P0);
        MP1 = add2(MP1, P1);
        MD0 = fma2(P0, S0, MD0);
        MD1 = fma2(P1, S1, MD1);
        ull U0 = fma2(S0, S0, v2);            // S'^2 - iv/ln2^2
        ull U1 = fma2(S1, S1, v2);
        DD0 = fma2(P0, U0, DD0);
        DD1 = fma2(P1, U1, DD1);
    }

    // ---- epilogue: h = ln2^2 * ( -0.5*(md'/mp)^2 + dd'/mp ) ----
    float h[4];
    {
        float mp0, mp1, md0, md1, dd0, dd1;
        upk2(MP0, mp0, mp1); upk2(MD0, md0, md1); upk2(DD0, dd0, dd1);
        float r0 = rcpf_fast(mp0), r1 = rcpf_fast(mp1);
        float dl0 = md0 * r0,      dl1 = md1 * r1;
        h[0] = LN2SQ_F * fmaf(-0.5f * dl0, dl0, dd0 * r0);
        h[1] = LN2SQ_F * fmaf(-0.5f * dl1, dl1, dd1 * r1);
        upk2(MP1, mp0, mp1); upk2(MD1, md0, md1); upk2(DD1, dd0, dd1);
        r0 = rcpf_fast(mp0); r1 = rcpf_fast(mp1);
        dl0 = md0 * r0;      dl1 = md1 * r1;
        h[2] = LN2SQ_F * fmaf(-0.5f * dl0, dl0, dd0 * r0);
        h[3] = LN2SQ_F * fmaf(-0.5f * dl1, dl1, dd1 * r1);
    }

    out4[base] = make_float4(h[0], h[1], h[2], h[3]);
}

extern "C" void kernel_launch(void* const* d_in, const int* in_sizes, int n_in,
                              void* d_out, int out_size) {
    const float4* x4        = (const float4*)d_in[0];
    const float*  mean      = (const float*)d_in[1];
    const float*  logvar    = (const float*)d_in[2];
    const float*  logweight = (const float*)d_in[3];
    float4*       out4      = (float4*)d_out;

    int n = in_sizes[0];                      // 4194304, divisible by 1024
    int blocks = n / ELEMS_PER_BLOCK;         // 4096
    gmm_hscore_kernel<<<blocks, TPB>>>(x4, mean, logvar, logweight, out4);
}